// round 14
// baseline (speedup 1.0000x reference)
#include <cuda_runtime.h>
#include <cstdint>

// Problem constants
#define Bn 4
#define Tn 64
#define Fn 32
#define Nn 512
#define Hn 64
#define SROWS 288
#define COLS_PER_CTA 16
#define CTAS_PER_B 32
#define NCTAS (Bn * CTAS_PER_B)   // 128 CTAs, 1/SM
#define NTHREADS 256
#define MB 32                     // k-chunk width
#define NCHUNK (Nn / MB)          // 16
#define NBUF 4                    // state ring depth (3 TMAs in flight)

#define CPITCH 36                 // chunk row pitch
#define PITCH_SST 260             // S^T half pitch
#define SST_HALF 256
#define PITCH_V  388
#define NV       384

#define CHUNK_FLOATS (SROWS * CPITCH)      // 10368
#define CHUNK_BYTES  (CHUNK_FLOATS * 4)    // 41472

// smem layout (float offsets)
#define OFF_MBAR   0                        // 8 (4 x 8B mbarriers)
#define OFF_STATE  16                       // 4*10368 = 41472 (byte 64, 16B aligned)
#define OFF_SST    41488                    // 16*260 = 4160
#define OFF_V      45648                    // 16*388 = 6208
#define OFF_BIAS   51856                    // 64
#define SMEM_FLOATS 51920
#define SMEM_BYTES  (SMEM_FLOATS * 4)       // 207680

// Persistent global state: chunk-major, rows pre-padded to CPITCH floats.
__device__ __align__(16) float g_state[2][Bn][NCHUNK][SROWS][CPITCH];
__device__ unsigned g_count = 0;
__device__ unsigned g_sense = 0;

__device__ __forceinline__ void grid_barrier(unsigned* lsense) {
    __syncthreads();
    if (threadIdx.x == 0) {
        __threadfence();
        unsigned s = (*lsense) ^ 1u;
        *lsense = s;
        unsigned old = atomicAdd(&g_count, 1u);
        if (old == NCTAS - 1u) {
            atomicExch(&g_count, 0u);
            __threadfence();
            atomicExch(&g_sense, s);
        } else {
            while (atomicAdd(&g_sense, 0u) != s) { __nanosleep(64); }
            __threadfence();
        }
    }
    __syncthreads();
}

__device__ __forceinline__ unsigned long long ffma2(unsigned long long a,
                                                    unsigned long long b,
                                                    unsigned long long c) {
    unsigned long long d;
    asm("fma.rn.f32x2 %0, %1, %2, %3;" : "=l"(d) : "l"(a), "l"(b), "l"(c));
    return d;
}
__device__ __forceinline__ float upsum(unsigned long long p) {
    float lo, hi;
    asm("mov.b64 {%0, %1}, %2;" : "=f"(lo), "=f"(hi) : "l"(p));
    return lo + hi;
}
__device__ __forceinline__ float to_tf32(float v) {
    float r;
    asm("cvt.rna.tf32.f32 %0, %1;" : "=f"(r) : "f"(v));
    return r;
}

// mma.sync m16n8k8 tf32 (sm_80+ PTX; compiles at compute_103)
__device__ __forceinline__ void mma_tf32(float& d0, float& d1, float& d2, float& d3,
                                         uint32_t a0, uint32_t a1, uint32_t a2, uint32_t a3,
                                         uint32_t b0, uint32_t b1) {
    asm volatile(
        "mma.sync.aligned.m16n8k8.row.col.f32.tf32.tf32.f32 "
        "{%0,%1,%2,%3}, {%4,%5,%6,%7}, {%8,%9}, {%0,%1,%2,%3};"
        : "+f"(d0), "+f"(d1), "+f"(d2), "+f"(d3)
        : "r"(a0), "r"(a1), "r"(a2), "r"(a3), "r"(b0), "r"(b1));
}

// mbarrier helpers
__device__ __forceinline__ void mbar_init(uint32_t addr, uint32_t count) {
    asm volatile("mbarrier.init.shared.b64 [%0], %1;" :: "r"(addr), "r"(count) : "memory");
}
__device__ __forceinline__ void mbar_expect_tx(uint32_t addr, uint32_t bytes) {
    asm volatile("mbarrier.arrive.expect_tx.shared.b64 _, [%0], %1;"
                 :: "r"(addr), "r"(bytes) : "memory");
}
__device__ __forceinline__ void mbar_wait(uint32_t addr, uint32_t parity) {
    uint32_t done;
    asm volatile(
        "{\n\t.reg .pred p;\n\t"
        "mbarrier.try_wait.parity.acquire.cta.shared::cta.b64 p, [%1], %2;\n\t"
        "selp.b32 %0, 1, 0, p;\n\t}"
        : "=r"(done) : "r"(addr), "r"(parity) : "memory");
    if (!done) {
        asm volatile(
            "{\n\t.reg .pred P1;\n\t"
            "WL_%=:\n\t"
            "mbarrier.try_wait.parity.acquire.cta.shared::cta.b64 P1, [%0], %1, 0x989680;\n\t"
            "@P1 bra.uni WD_%=;\n\t"
            "bra.uni WL_%=;\n\t"
            "WD_%=:\n\t}"
            :: "r"(addr), "r"(parity) : "memory");
    }
}
__device__ __forceinline__ void bulk_copy(uint32_t dst_smem, const void* src, uint32_t bytes,
                                          uint32_t mbar) {
    asm volatile(
        "cp.async.bulk.shared::cta.global.mbarrier::complete_tx::bytes [%0], [%1], %2, [%3];"
        :: "r"(dst_smem), "l"(src), "r"(bytes), "r"(mbar) : "memory");
}

__global__ void __launch_bounds__(NTHREADS, 1)
hs_db_kernel(const float* __restrict__ x,      // (B,T,F,N)
             const float* __restrict__ z0,     // (B,H,N)
             const float* __restrict__ S,      // (B,T,1,N,N)
             const float* __restrict__ aW,     // (H,1,K,F) -> h*128 + j
             const float* __restrict__ bW,     // (H,1,K,H) -> h*256 + j
             const float* __restrict__ xBias,  // (H,1)
             const float* __restrict__ zBias,  // (H,1)
             float* __restrict__ out)          // (B,T,H,N)
{
    extern __shared__ float sm[];
    float* sbias = sm + OFF_BIAS;
    float* sST   = sm + OFF_SST;    // [16][260] S^T half, tf32-rounded
    float* sV    = sm + OFF_V;

    const int tid  = threadIdx.x;
    const int b    = blockIdx.x / CTAS_PER_B;
    const int col0 = (blockIdx.x % CTAS_PER_B) * COLS_PER_CTA;
    const int kc0  = col0 >> 5;           // this CTA's write chunk
    const int cmb  = col0 & 31;           // 0 or 16 within chunk

    // mma mapping
    const int wid  = tid >> 5;            // warp 0..7; m-groups {wid, wid+8, wid+16<18}
    const int lane = tid & 31;
    const int gid  = lane >> 2;           // groupID 0..7
    const int tid4 = lane & 3;            // threadID_in_group
    // phase-2 mapping
    const int hq  = tid >> 4;             // 0..15; h in {hq,hq+16,hq+32,hq+48}
    const int cc2 = tid & 15;

    const uint32_t smem_u32 = (uint32_t)__cvta_generic_to_shared(sm);
    const uint32_t mbar_base = smem_u32 + OFF_MBAR * 4;      // 4 x 8B
    const uint32_t st_base   = smem_u32 + OFF_STATE * 4;

    if (tid == 0) {
#pragma unroll
        for (int s = 0; s < NBUF; ++s) mbar_init(mbar_base + 8 * s, 1);
    }

    if (tid < Hn) sbias[tid] = xBias[tid] + zBias[tid];

    // Init: zero this CTA's state columns; sV z-region <- z0
    for (int i = tid; i < SROWS * COLS_PER_CTA; i += NTHREADS) {
        int r = i >> 4, cc = i & 15;
        g_state[0][b][kc0][r][cmb + cc] = 0.0f;
    }
    for (int i = tid; i < Hn * COLS_PER_CTA; i += NTHREADS) {
        int g = i >> 4, cc = i & 15;
        sV[cc * PITCH_V + 128 + g] = z0[(b * Hn + g) * Nn + col0 + cc];
    }

    unsigned lsense = 0;
    grid_barrier(&lsense);   // barrier #1 (orders mbarrier init + state zero)

    for (int t = 0; t < Tn; ++t) {
        const int cur = t & 1;
        const int nxt = cur ^ 1;
        const int base = t * NCHUNK;
        const float* Sbt = S + (size_t)(b * Tn + t) * Nn * Nn;
        const float* xbt = x + (size_t)(b * Tn + t) * Fn * Nn;
        const float* gst = &g_state[cur][b][0][0][0];

        // prologue: launch TMAs for chunks 0..2 (buffers 0..2 free from t-1)
        if (tid == 0) {
#pragma unroll
            for (int i = 0; i < 3; ++i) {
                const int idx = base + i;
                const int sl = idx & 3;
                mbar_expect_tx(mbar_base + 8 * sl, CHUNK_BYTES);
                bulk_copy(st_base + sl * CHUNK_BYTES, gst + (size_t)i * CHUNK_FLOATS,
                          CHUNK_BYTES, mbar_base + 8 * sl);
            }
        }

        // Stage x(t) -> sV[cc][0..31]
        for (int i = tid; i < Fn * 16; i += NTHREADS) {
            int f = i >> 4, cc = i & 15;
            sV[cc * PITCH_V + f] = xbt[f * Nn + col0 + cc];
        }
        // Stage S^T half 0 (tf32-rounded): sST[c][k] for k=0..255
        {
            const float* srow = Sbt + (size_t)tid * Nn + col0;
            float4 v0 = *reinterpret_cast<const float4*>(srow);
            float4 v1 = *reinterpret_cast<const float4*>(srow + 4);
            float4 v2 = *reinterpret_cast<const float4*>(srow + 8);
            float4 v3 = *reinterpret_cast<const float4*>(srow + 12);
            float* d = sST + tid;
            d[0 * PITCH_SST]  = to_tf32(v0.x); d[1 * PITCH_SST]  = to_tf32(v0.y);
            d[2 * PITCH_SST]  = to_tf32(v0.z); d[3 * PITCH_SST]  = to_tf32(v0.w);
            d[4 * PITCH_SST]  = to_tf32(v1.x); d[5 * PITCH_SST]  = to_tf32(v1.y);
            d[6 * PITCH_SST]  = to_tf32(v1.z); d[7 * PITCH_SST]  = to_tf32(v1.w);
            d[8 * PITCH_SST]  = to_tf32(v2.x); d[9 * PITCH_SST]  = to_tf32(v2.y);
            d[10 * PITCH_SST] = to_tf32(v2.z); d[11 * PITCH_SST] = to_tf32(v2.w);
            d[12 * PITCH_SST] = to_tf32(v3.x); d[13 * PITCH_SST] = to_tf32(v3.y);
            d[14 * PITCH_SST] = to_tf32(v3.z); d[15 * PITCH_SST] = to_tf32(v3.w);
        }
        __syncthreads();                 // sST half0 + sV.x ready

        // acc[mgi][nt][4] — full-K accumulators in registers
        float acc[3][2][4];
#pragma unroll
        for (int i = 0; i < 3; ++i)
#pragma unroll
            for (int n = 0; n < 2; ++n)
#pragma unroll
                for (int q = 0; q < 4; ++q) acc[i][n][q] = 0.0f;

        for (int c = 0; c < NCHUNK; ++c) {
            const int idx = base + c;
            const int sl = idx & 3;
            // keep 3 TMAs in flight: issue chunk c+3 (its buffer freed at end of c-1)
            if (c + 3 < NCHUNK && tid == 0) {
                const int fidx = idx + 3;
                const int fsl = fidx & 3;
                mbar_expect_tx(mbar_base + 8 * fsl, CHUNK_BYTES);
                bulk_copy(st_base + fsl * CHUNK_BYTES,
                          gst + (size_t)(c + 3) * CHUNK_FLOATS, CHUNK_BYTES,
                          mbar_base + 8 * fsl);
            }
            mbar_wait(mbar_base + 8 * sl, (uint32_t)((idx >> 2) & 1));
            // compute chunk c: 4 k8-steps
            {
                const float* slot = sm + OFF_STATE + sl * CHUNK_FLOATS;
                const int kkb = ((c & 7) << 5);   // sST local k base for this chunk
#pragma unroll
                for (int ks = 0; ks < 4; ++ks) {
                    const int kl = (ks << 3) + tid4;      // chunk-local k col
                    const int kk = kkb + (ks << 3) + tid4;
                    uint32_t bfr[2][2];
#pragma unroll
                    for (int nt = 0; nt < 2; ++nt) {
                        const float* bp = sST + (8 * nt + gid) * PITCH_SST + kk;
                        bfr[nt][0] = __float_as_uint(bp[0]);
                        bfr[nt][1] = __float_as_uint(bp[4]);
                    }
#pragma unroll
                    for (int i = 0; i < 3; ++i) {
                        const int mg = wid + 8 * i;
                        if (mg < 18) {
                            const float* ap = slot + (16 * mg + gid) * CPITCH + kl;
                            uint32_t a0 = __float_as_uint(ap[0]);
                            uint32_t a1 = __float_as_uint(ap[8 * CPITCH]);
                            uint32_t a2 = __float_as_uint(ap[4]);
                            uint32_t a3 = __float_as_uint(ap[8 * CPITCH + 4]);
                            mma_tf32(acc[i][0][0], acc[i][0][1], acc[i][0][2], acc[i][0][3],
                                     a0, a1, a2, a3, bfr[0][0], bfr[0][1]);
                            mma_tf32(acc[i][1][0], acc[i][1][1], acc[i][1][2], acc[i][1][3],
                                     a0, a1, a2, a3, bfr[1][0], bfr[1][1]);
                        }
                    }
                }
            }
            // mid-t: restage S^T half 1 (needs all reads of half 0 done)
            if (c == 7) {
                __syncthreads();
                const float* srow = Sbt + (size_t)(SST_HALF + tid) * Nn + col0;
                float4 v0 = *reinterpret_cast<const float4*>(srow);
                float4 v1 = *reinterpret_cast<const float4*>(srow + 4);
                float4 v2 = *reinterpret_cast<const float4*>(srow + 8);
                float4 v3 = *reinterpret_cast<const float4*>(srow + 12);
                float* d = sST + tid;
                d[0 * PITCH_SST]  = to_tf32(v0.x); d[1 * PITCH_SST]  = to_tf32(v0.y);
                d[2 * PITCH_SST]  = to_tf32(v0.z); d[3 * PITCH_SST]  = to_tf32(v0.w);
                d[4 * PITCH_SST]  = to_tf32(v1.x); d[5 * PITCH_SST]  = to_tf32(v1.y);
                d[6 * PITCH_SST]  = to_tf32(v1.z); d[7 * PITCH_SST]  = to_tf32(v1.w);
                d[8 * PITCH_SST]  = to_tf32(v2.x); d[9 * PITCH_SST]  = to_tf32(v2.y);
                d[10 * PITCH_SST] = to_tf32(v2.z); d[11 * PITCH_SST] = to_tf32(v2.w);
                d[12 * PITCH_SST] = to_tf32(v3.x); d[13 * PITCH_SST] = to_tf32(v3.y);
                d[14 * PITCH_SST] = to_tf32(v3.z); d[15 * PITCH_SST] = to_tf32(v3.w);
            }
            __syncthreads();             // buffer-free handoff + half1 visibility
        }

        // Write Y (acc) into transposed sV: row<96 -> j=32+row ; row>=96 -> j=96+row
#pragma unroll
        for (int i = 0; i < 3; ++i) {
            const int mg = wid + 8 * i;
            if (mg < 18) {
                const int r_lo = 16 * mg + gid;
                const int r_hi = r_lo + 8;
                const int j_lo = (r_lo < 96) ? (32 + r_lo) : (96 + r_lo);
                const int j_hi = (r_hi < 96) ? (32 + r_hi) : (96 + r_hi);
#pragma unroll
                for (int nt = 0; nt < 2; ++nt) {
                    const int cl = 8 * nt + 2 * tid4;
                    sV[cl * PITCH_V + j_lo]       = acc[i][nt][0];
                    sV[(cl + 1) * PITCH_V + j_lo] = acc[i][nt][1];
                    sV[cl * PITCH_V + j_hi]       = acc[i][nt][2];
                    sV[(cl + 1) * PITCH_V + j_hi] = acc[i][nt][3];
                }
            }
        }
        __syncthreads();

        // Phase 2: pre[h,c] = bias[h] + sum_j w[h][j] * sV[c][j]
        // weights streamed from global (L2-hot, 16-lane broadcast LDG.128)
        unsigned long long pa[4] = {0ull, 0ull, 0ull, 0ull};
        {
            const float* vp = sV + cc2 * PITCH_V;
#pragma unroll 4
            for (int j = 0; j < 128; j += 4) {
                ulonglong2 v = *reinterpret_cast<const ulonglong2*>(vp + j);
#pragma unroll
                for (int i = 0; i < 4; ++i) {
                    ulonglong2 w = __ldg(reinterpret_cast<const ulonglong2*>(
                        aW + (hq + 16 * i) * 128 + j));
                    pa[i] = ffma2(w.x, v.x, pa[i]);
                    pa[i] = ffma2(w.y, v.y, pa[i]);
                }
            }
#pragma unroll 4
            for (int j = 0; j < 256; j += 4) {
                ulonglong2 v = *reinterpret_cast<const ulonglong2*>(vp + 128 + j);
#pragma unroll
                for (int i = 0; i < 4; ++i) {
                    ulonglong2 w = __ldg(reinterpret_cast<const ulonglong2*>(
                        bW + (hq + 16 * i) * 256 + j));
                    pa[i] = ffma2(w.x, v.x, pa[i]);
                    pa[i] = ffma2(w.y, v.y, pa[i]);
                }
            }
        }
        float zv[4];
#pragma unroll
        for (int i = 0; i < 4; ++i)
            zv[i] = tanhf(sbias[hq + 16 * i] + upsum(pa[i]));

        // State shift for t+1 (column-local STG, tf32-rounded for the MMA A side)
        {
            float* gnxt = &g_state[nxt][b][kc0][0][0];
#pragma unroll
            for (int it = 0; it < 18; ++it) {
                int i = tid + it * NTHREADS;
                int r = i >> 4, cc = i & 15;
                int j = (r < 96) ? r : (r + 32);
                gnxt[r * CPITCH + cmb + cc] = to_tf32(sV[cc * PITCH_V + j]);
            }
        }
        __syncthreads();   // all reads of z(t-1) done before overwrite

        // write z(t) -> out + sV z-region
#pragma unroll
        for (int i = 0; i < 4; ++i) {
            int h = hq + 16 * i;
            out[(((size_t)b * Tn + t) * Hn + h) * Nn + col0 + cc2] = zv[i];
            sV[cc2 * PITCH_V + 128 + h] = zv[i];
        }

        grid_barrier(&lsense);   // barriers #2..#65
    }

    grid_barrier(&lsense);       // barrier #66 (even parity per launch)
}

extern "C" void kernel_launch(void* const* d_in, const int* in_sizes, int n_in,
                              void* d_out, int out_size) {
    const float* x     = (const float*)d_in[0];
    const float* z0    = (const float*)d_in[1];
    const float* S     = (const float*)d_in[2];
    const float* aW    = (const float*)d_in[3];
    const float* bW    = (const float*)d_in[4];
    const float* xBias = (const float*)d_in[5];
    const float* zBias = (const float*)d_in[6];
    float* out = (float*)d_out;

    cudaFuncSetAttribute(hs_db_kernel,
                         cudaFuncAttributeMaxDynamicSharedMemorySize, SMEM_BYTES);
    hs_db_kernel<<<NCTAS, NTHREADS, SMEM_BYTES>>>(x, z0, S, aW, bW, xBias, zBias, out);
}

// round 15
// speedup vs baseline: 1.3705x; 1.3705x over previous
#include <cuda_runtime.h>
#include <cuda_fp16.h>
#include <cstdint>

// Problem constants
#define Bn 4
#define Tn 64
#define Fn 32
#define Nn 512
#define Hn 64
#define SROWS 288
#define COLS_PER_CTA 16
#define CTAS_PER_B 32
#define NCTAS (Bn * CTAS_PER_B)   // 128 CTAs, 1/SM
#define NTHREADS 256
#define MB 32                     // k-chunk width (halves)
#define NCHUNK (Nn / MB)          // 16
#define NBUF 4                    // state ring depth (3 TMAs in flight)

#define CPITCH_H 36               // chunk row pitch in halves (18 words, conflict-free)
#define CPITCH_W 18
#define PITCH_SST_H 520           // S^T pitch in halves (260 words, conflict-free)
#define PITCH_SST_W 260
#define PITCH_V  388
#define NV       384

#define CHUNK_HALVES (SROWS * CPITCH_H)     // 10368 halves
#define CHUNK_BYTES  (CHUNK_HALVES * 2)     // 20736
#define CHUNK_WORDS  (CHUNK_HALVES / 2)     // 5184

// smem layout (word/float offsets)
#define OFF_W      0                        // 24576 (weights fp32)
#define OFF_BIAS   24576                    // 64
#define OFF_MBAR   24640                    // 8 (4 x 8B mbarriers)
#define OFF_STATE  24648                    // 4*5184 = 20736 words (byte 98592, 16B ok)
#define OFF_SST    45384                    // 16*260 = 4160 words (fp16 S^T)
#define OFF_V      49544                    // 16*388 = 6208
#define SMEM_FLOATS 55752
#define SMEM_BYTES  (SMEM_FLOATS * 4)       // 223008 <= 232448

// Persistent global state: fp16, chunk-major, rows padded to CPITCH_H halves.
__device__ __align__(16) __half g_state[2][Bn][NCHUNK][SROWS][CPITCH_H];
__device__ unsigned g_count = 0;
__device__ unsigned g_sense = 0;

__device__ __forceinline__ void grid_barrier(unsigned* lsense) {
    __syncthreads();
    if (threadIdx.x == 0) {
        __threadfence();
        unsigned s = (*lsense) ^ 1u;
        *lsense = s;
        unsigned old = atomicAdd(&g_count, 1u);
        if (old == NCTAS - 1u) {
            atomicExch(&g_count, 0u);
            __threadfence();
            atomicExch(&g_sense, s);
        } else {
            while (atomicAdd(&g_sense, 0u) != s) { __nanosleep(64); }
            __threadfence();
        }
    }
    __syncthreads();
}

__device__ __forceinline__ unsigned long long ffma2(unsigned long long a,
                                                    unsigned long long b,
                                                    unsigned long long c) {
    unsigned long long d;
    asm("fma.rn.f32x2 %0, %1, %2, %3;" : "=l"(d) : "l"(a), "l"(b), "l"(c));
    return d;
}
__device__ __forceinline__ float upsum(unsigned long long p) {
    float lo, hi;
    asm("mov.b64 {%0, %1}, %2;" : "=f"(lo), "=f"(hi) : "l"(p));
    return lo + hi;
}

// mma.sync m16n8k16 f16 with f32 accumulate (sm_80 PTX; fine at compute_103)
__device__ __forceinline__ void mma_f16(float& d0, float& d1, float& d2, float& d3,
                                        uint32_t a0, uint32_t a1, uint32_t a2, uint32_t a3,
                                        uint32_t b0, uint32_t b1) {
    asm volatile(
        "mma.sync.aligned.m16n8k16.row.col.f32.f16.f16.f32 "
        "{%0,%1,%2,%3}, {%4,%5,%6,%7}, {%8,%9}, {%0,%1,%2,%3};"
        : "+f"(d0), "+f"(d1), "+f"(d2), "+f"(d3)
        : "r"(a0), "r"(a1), "r"(a2), "r"(a3), "r"(b0), "r"(b1));
}

// mbarrier helpers
__device__ __forceinline__ void mbar_init(uint32_t addr, uint32_t count) {
    asm volatile("mbarrier.init.shared.b64 [%0], %1;" :: "r"(addr), "r"(count) : "memory");
}
__device__ __forceinline__ void mbar_expect_tx(uint32_t addr, uint32_t bytes) {
    asm volatile("mbarrier.arrive.expect_tx.shared.b64 _, [%0], %1;"
                 :: "r"(addr), "r"(bytes) : "memory");
}
__device__ __forceinline__ void mbar_wait(uint32_t addr, uint32_t parity) {
    uint32_t done;
    asm volatile(
        "{\n\t.reg .pred p;\n\t"
        "mbarrier.try_wait.parity.acquire.cta.shared::cta.b64 p, [%1], %2;\n\t"
        "selp.b32 %0, 1, 0, p;\n\t}"
        : "=r"(done) : "r"(addr), "r"(parity) : "memory");
    if (!done) {
        asm volatile(
            "{\n\t.reg .pred P1;\n\t"
            "WL_%=:\n\t"
            "mbarrier.try_wait.parity.acquire.cta.shared::cta.b64 P1, [%0], %1, 0x989680;\n\t"
            "@P1 bra.uni WD_%=;\n\t"
            "bra.uni WL_%=;\n\t"
            "WD_%=:\n\t}"
            :: "r"(addr), "r"(parity) : "memory");
    }
}
__device__ __forceinline__ void bulk_copy(uint32_t dst_smem, const void* src, uint32_t bytes,
                                          uint32_t mbar) {
    asm volatile(
        "cp.async.bulk.shared::cta.global.mbarrier::complete_tx::bytes [%0], [%1], %2, [%3];"
        :: "r"(dst_smem), "l"(src), "r"(bytes), "r"(mbar) : "memory");
}

__global__ void __launch_bounds__(NTHREADS, 1)
hs_db_kernel(const float* __restrict__ x,      // (B,T,F,N)
             const float* __restrict__ z0,     // (B,H,N)
             const float* __restrict__ S,      // (B,T,1,N,N)
             const float* __restrict__ aW,     // (H,1,K,F)
             const float* __restrict__ bW,     // (H,1,K,H)
             const float* __restrict__ xBias,  // (H,1)
             const float* __restrict__ zBias,  // (H,1)
             float* __restrict__ out)          // (B,T,H,N)
{
    extern __shared__ float sm[];
    float* sW    = sm + OFF_W;
    float* sbias = sm + OFF_BIAS;
    uint32_t* sSTw = reinterpret_cast<uint32_t*>(sm + OFF_SST);   // fp16x2 words
    __half*   sSTh = reinterpret_cast<__half*>(sm + OFF_SST);
    float* sV    = sm + OFF_V;

    const int tid  = threadIdx.x;
    const int b    = blockIdx.x / CTAS_PER_B;
    const int col0 = (blockIdx.x % CTAS_PER_B) * COLS_PER_CTA;
    const int kc0  = col0 >> 5;           // this CTA's write chunk
    const int cmb  = col0 & 31;           // 0 or 16 within chunk

    // mma mapping
    const int wid  = tid >> 5;            // warp 0..7; m-groups {wid, wid+8, wid+16<18}
    const int lane = tid & 31;
    const int gid  = lane >> 2;           // groupID 0..7
    const int tid4 = lane & 3;            // threadID_in_group
    // phase-2 mapping
    const int hq  = tid >> 4;             // 0..15; h in {hq,hq+16,hq+32,hq+48}
    const int cc2 = tid & 15;

    const uint32_t smem_u32 = (uint32_t)__cvta_generic_to_shared(sm);
    const uint32_t mbar_base = smem_u32 + OFF_MBAR * 4;      // 4 x 8B
    const uint32_t st_base   = smem_u32 + OFF_STATE * 4;

    if (tid == 0) {
#pragma unroll
        for (int s = 0; s < NBUF; ++s) mbar_init(mbar_base + 8 * s, 1);
    }

    // Load fused weights once (fp32, smem): sW[h][0..127]=aW, [128..383]=bW
    for (int i = tid; i < Hn * 128; i += NTHREADS) {
        int h = i >> 7, j = i & 127;
        sW[h * NV + j] = aW[i];
    }
    for (int i = tid; i < Hn * 256; i += NTHREADS) {
        int h = i >> 8, j = i & 255;
        sW[h * NV + 128 + j] = bW[i];
    }
    if (tid < Hn) sbias[tid] = xBias[tid] + zBias[tid];

    // Init: zero this CTA's state columns; sV z-region <- z0
    for (int i = tid; i < SROWS * COLS_PER_CTA; i += NTHREADS) {
        int r = i >> 4, cc = i & 15;
        g_state[0][b][kc0][r][cmb + cc] = __float2half(0.0f);
    }
    for (int i = tid; i < Hn * COLS_PER_CTA; i += NTHREADS) {
        int g = i >> 4, cc = i & 15;
        sV[cc * PITCH_V + 128 + g] = z0[(b * Hn + g) * Nn + col0 + cc];
    }

    unsigned lsense = 0;
    grid_barrier(&lsense);   // barrier #1 (orders mbarrier init + state zero)

    for (int t = 0; t < Tn; ++t) {
        const int cur = t & 1;
        const int nxt = cur ^ 1;
        const int base = t * NCHUNK;
        const float* Sbt = S + (size_t)(b * Tn + t) * Nn * Nn;
        const float* xbt = x + (size_t)(b * Tn + t) * Fn * Nn;
        const __half* gst = &g_state[cur][b][0][0][0];

        // prologue: launch TMAs for chunks 0..2 (buffers freed at end of t-1)
        if (tid == 0) {
#pragma unroll
            for (int i = 0; i < 3; ++i) {
                const int idx = base + i;
                const int sl = idx & 3;
                mbar_expect_tx(mbar_base + 8 * sl, CHUNK_BYTES);
                bulk_copy(st_base + sl * CHUNK_BYTES,
                          gst + (size_t)i * CHUNK_HALVES, CHUNK_BYTES,
                          mbar_base + 8 * sl);
            }
        }

        // Stage x(t) -> sV[cc][0..31]  (fp32, used by phase 2 tap 0)
        for (int i = tid; i < Fn * 16; i += NTHREADS) {
            int f = i >> 4, cc = i & 15;
            sV[cc * PITCH_V + f] = xbt[f * Nn + col0 + cc];
        }
        // Stage FULL S^T (fp16): sSTh[c*520 + k], k=0..511 (2 k-rows per thread)
#pragma unroll
        for (int r2 = 0; r2 < 2; ++r2) {
            const int k = tid + 256 * r2;
            const float* srow = Sbt + (size_t)k * Nn + col0;
            float4 v0 = *reinterpret_cast<const float4*>(srow);
            float4 v1 = *reinterpret_cast<const float4*>(srow + 4);
            float4 v2 = *reinterpret_cast<const float4*>(srow + 8);
            float4 v3 = *reinterpret_cast<const float4*>(srow + 12);
            float vv[16] = {v0.x, v0.y, v0.z, v0.w, v1.x, v1.y, v1.z, v1.w,
                            v2.x, v2.y, v2.z, v2.w, v3.x, v3.y, v3.z, v3.w};
#pragma unroll
            for (int c = 0; c < 16; ++c)
                sSTh[c * PITCH_SST_H + k] = __float2half(vv[c]);
        }
        __syncthreads();                 // S^T + sV.x ready

        // acc[mgi][nt][4] — full-K fp32 accumulators
        float acc[3][2][4];
#pragma unroll
        for (int i = 0; i < 3; ++i)
#pragma unroll
            for (int n = 0; n < 2; ++n)
#pragma unroll
                for (int q = 0; q < 4; ++q) acc[i][n][q] = 0.0f;

        for (int c = 0; c < NCHUNK; ++c) {
            const int idx = base + c;
            const int sl = idx & 3;
            // keep 3 TMAs in flight: issue chunk c+3 (buffer freed end of c-1)
            if (c + 3 < NCHUNK && tid == 0) {
                const int fidx = idx + 3;
                const int fsl = fidx & 3;
                mbar_expect_tx(mbar_base + 8 * fsl, CHUNK_BYTES);
                bulk_copy(st_base + fsl * CHUNK_BYTES,
                          gst + (size_t)(c + 3) * CHUNK_HALVES, CHUNK_BYTES,
                          mbar_base + 8 * fsl);
            }
            mbar_wait(mbar_base + 8 * sl, (uint32_t)((idx >> 2) & 1));
            // compute chunk c: 2 k16-steps
            {
                const uint32_t* slotw = reinterpret_cast<const uint32_t*>(sm + OFF_STATE)
                                        + sl * CHUNK_WORDS;
                const int sstkb = 16 * c;             // S^T word base for this chunk
#pragma unroll
                for (int ks = 0; ks < 2; ++ks) {
                    const int aw = 8 * ks + tid4;     // A word offset within row
                    const int bw = sstkb + 8 * ks + tid4;
                    uint32_t bfr[2][2];
#pragma unroll
                    for (int nt = 0; nt < 2; ++nt) {
                        const uint32_t* bp = sSTw + (8 * nt + gid) * PITCH_SST_W + bw;
                        bfr[nt][0] = bp[0];
                        bfr[nt][1] = bp[4];
                    }
#pragma unroll
                    for (int i = 0; i < 3; ++i) {
                        const int mg = wid + 8 * i;
                        if (mg < 18) {
                            const uint32_t* ap = slotw + (16 * mg + gid) * CPITCH_W + aw;
                            uint32_t a0 = ap[0];
                            uint32_t a1 = ap[8 * CPITCH_W];
                            uint32_t a2 = ap[4];
                            uint32_t a3 = ap[8 * CPITCH_W + 4];
                            mma_f16(acc[i][0][0], acc[i][0][1], acc[i][0][2], acc[i][0][3],
                                    a0, a1, a2, a3, bfr[0][0], bfr[0][1]);
                            mma_f16(acc[i][1][0], acc[i][1][1], acc[i][1][2], acc[i][1][3],
                                    a0, a1, a2, a3, bfr[1][0], bfr[1][1]);
                        }
                    }
                }
            }
            __syncthreads();             // buffer-free handoff
        }

        // Write Y (acc) into transposed sV: row<96 -> j=32+row ; row>=96 -> j=96+row
#pragma unroll
        for (int i = 0; i < 3; ++i) {
            const int mg = wid + 8 * i;
            if (mg < 18) {
                const int r_lo = 16 * mg + gid;
                const int r_hi = r_lo + 8;
                const int j_lo = (r_lo < 96) ? (32 + r_lo) : (96 + r_lo);
                const int j_hi = (r_hi < 96) ? (32 + r_hi) : (96 + r_hi);
#pragma unroll
                for (int nt = 0; nt < 2; ++nt) {
                    const int cl = 8 * nt + 2 * tid4;
                    sV[cl * PITCH_V + j_lo]       = acc[i][nt][0];
                    sV[(cl + 1) * PITCH_V + j_lo] = acc[i][nt][1];
                    sV[cl * PITCH_V + j_hi]       = acc[i][nt][2];
                    sV[(cl + 1) * PITCH_V + j_hi] = acc[i][nt][3];
                }
            }
        }
        __syncthreads();

        // Phase 2: pre[h,c] = bias[h] + sum_j sW[h][j] * sV[c][j]  (fp32, smem weights)
        unsigned long long pa[4] = {0ull, 0ull, 0ull, 0ull};
        {
            const float* vp = sV + cc2 * PITCH_V;
#pragma unroll 4
            for (int j = 0; j < NV; j += 4) {
                ulonglong2 v = *reinterpret_cast<const ulonglong2*>(vp + j);
#pragma unroll
                for (int i = 0; i < 4; ++i) {
                    ulonglong2 w = *reinterpret_cast<const ulonglong2*>(
                        sW + (hq + 16 * i) * NV + j);
                    pa[i] = ffma2(w.x, v.x, pa[i]);
                    pa[i] = ffma2(w.y, v.y, pa[i]);
                }
            }
        }
        float zv[4];
#pragma unroll
        for (int i = 0; i < 4; ++i)
            zv[i] = tanhf(sbias[hq + 16 * i] + upsum(pa[i]));

        // State shift for t+1 (column-local fp16 STG)
        {
            __half* gnxt = &g_state[nxt][b][kc0][0][0];
#pragma unroll
            for (int it = 0; it < 18; ++it) {
                int i = tid + it * NTHREADS;
                int r = i >> 4, cc = i & 15;
                int j = (r < 96) ? r : (r + 32);
                gnxt[r * CPITCH_H + cmb + cc] = __float2half(sV[cc * PITCH_V + j]);
            }
        }
        __syncthreads();   // all reads of z(t-1) done before overwrite

        // write z(t) -> out + sV z-region
#pragma unroll
        for (int i = 0; i < 4; ++i) {
            int h = hq + 16 * i;
            out[(((size_t)b * Tn + t) * Hn + h) * Nn + col0 + cc2] = zv[i];
            sV[cc2 * PITCH_V + 128 + h] = zv[i];
        }

        grid_barrier(&lsense);   // barriers #2..#65
    }

    grid_barrier(&lsense);       // barrier #66 (even parity per launch)
}

extern "C" void kernel_launch(void* const* d_in, const int* in_sizes, int n_in,
                              void* d_out, int out_size) {
    const float* x     = (const float*)d_in[0];
    const float* z0    = (const float*)d_in[1];
    const float* S     = (const float*)d_in[2];
    const float* aW    = (const float*)d_in[3];
    const float* bW    = (const float*)d_in[4];
    const float* xBias = (const float*)d_in[5];
    const float* zBias = (const float*)d_in[6];
    float* out = (float*)d_out;

    cudaFuncSetAttribute(hs_db_kernel,
                         cudaFuncAttributeMaxDynamicSharedMemorySize, SMEM_BYTES);
    hs_db_kernel<<<NCTAS, NTHREADS, SMEM_BYTES>>>(x, z0, S, aW, bW, xBias, zBias, out);
}

// round 16
// speedup vs baseline: 2.0768x; 1.5153x over previous
#include <cuda_runtime.h>
#include <cuda_fp16.h>
#include <cstdint>

// Problem constants
#define Bn 4
#define Tn 64
#define Fn 32
#define Nn 512
#define Hn 64
#define SROWS 288
#define COLS_PER_CTA 16
#define CTAS_PER_B 32
#define NCTAS (Bn * CTAS_PER_B)   // 128 CTAs, 1/SM
#define NTHREADS 256
#define MB 64                     // k-chunk width (halves)
#define NCHUNK (Nn / MB)          // 8
#define NBUF 3                    // state ring depth (3 TMAs in flight)

#define CPITCH_H 72               // chunk row pitch halves (36 words -> banks 4*gid)
#define CPITCH_W 36
#define PITCH_SST_H 520           // S^T pitch halves (260 words)
#define PITCH_SST_W 260
#define PV_H 392                  // sV / sW pitch halves (196 words -> banks 4*gid)
#define PV_W 196
#define NV 384

#define CHUNK_HALVES (SROWS * CPITCH_H)     // 20736
#define CHUNK_BYTES  (CHUNK_HALVES * 2)     // 41472
#define CHUNK_WORDS  (CHUNK_HALVES / 2)     // 10368

// smem layout (float offsets)
#define OFF_MBAR   0                        // 8 floats (3 x 8B mbarriers + pad)
#define OFF_STATE  8                        // 3*10368 = 31104 words (byte 32, 16B ok)
#define OFF_SST    31112                    // 16*260 = 4160 words (fp16 S^T)
#define OFF_V      35272                    // 16*196 = 3136 words (fp16 V, col-major)
#define OFF_W      38408                    // 64*196 = 12544 words (fp16 weights)
#define OFF_BIAS   50952                    // 64 floats
#define SMEM_FLOATS 51016
#define SMEM_BYTES  (SMEM_FLOATS * 4)       // 204064 <= 232448

// Persistent global state: fp16, chunk-major, rows padded to CPITCH_H halves.
__device__ __align__(16) __half g_state[2][Bn][NCHUNK][SROWS][CPITCH_H];
__device__ unsigned g_count = 0;
__device__ unsigned g_sense = 0;

__device__ __forceinline__ void grid_barrier(unsigned* lsense) {
    __syncthreads();
    if (threadIdx.x == 0) {
        __threadfence();
        unsigned s = (*lsense) ^ 1u;
        *lsense = s;
        unsigned old = atomicAdd(&g_count, 1u);
        if (old == NCTAS - 1u) {
            atomicExch(&g_count, 0u);
            __threadfence();
            atomicExch(&g_sense, s);
        } else {
            while (atomicAdd(&g_sense, 0u) != s) { __nanosleep(64); }
            __threadfence();
        }
    }
    __syncthreads();
}

// mma.sync m16n8k16 f16 with f32 accumulate
__device__ __forceinline__ void mma_f16(float& d0, float& d1, float& d2, float& d3,
                                        uint32_t a0, uint32_t a1, uint32_t a2, uint32_t a3,
                                        uint32_t b0, uint32_t b1) {
    asm volatile(
        "mma.sync.aligned.m16n8k16.row.col.f32.f16.f16.f32 "
        "{%0,%1,%2,%3}, {%4,%5,%6,%7}, {%8,%9}, {%0,%1,%2,%3};"
        : "+f"(d0), "+f"(d1), "+f"(d2), "+f"(d3)
        : "r"(a0), "r"(a1), "r"(a2), "r"(a3), "r"(b0), "r"(b1));
}

// mbarrier helpers
__device__ __forceinline__ void mbar_init(uint32_t addr, uint32_t count) {
    asm volatile("mbarrier.init.shared.b64 [%0], %1;" :: "r"(addr), "r"(count) : "memory");
}
__device__ __forceinline__ void mbar_expect_tx(uint32_t addr, uint32_t bytes) {
    asm volatile("mbarrier.arrive.expect_tx.shared.b64 _, [%0], %1;"
                 :: "r"(addr), "r"(bytes) : "memory");
}
__device__ __forceinline__ void mbar_wait(uint32_t addr, uint32_t parity) {
    uint32_t done;
    asm volatile(
        "{\n\t.reg .pred p;\n\t"
        "mbarrier.try_wait.parity.acquire.cta.shared::cta.b64 p, [%1], %2;\n\t"
        "selp.b32 %0, 1, 0, p;\n\t}"
        : "=r"(done) : "r"(addr), "r"(parity) : "memory");
    if (!done) {
        asm volatile(
            "{\n\t.reg .pred P1;\n\t"
            "WL_%=:\n\t"
            "mbarrier.try_wait.parity.acquire.cta.shared::cta.b64 P1, [%0], %1, 0x989680;\n\t"
            "@P1 bra.uni WD_%=;\n\t"
            "bra.uni WL_%=;\n\t"
            "WD_%=:\n\t}"
            :: "r"(addr), "r"(parity) : "memory");
    }
}
__device__ __forceinline__ void bulk_copy(uint32_t dst_smem, const void* src, uint32_t bytes,
                                          uint32_t mbar) {
    asm volatile(
        "cp.async.bulk.shared::cta.global.mbarrier::complete_tx::bytes [%0], [%1], %2, [%3];"
        :: "r"(dst_smem), "l"(src), "r"(bytes), "r"(mbar) : "memory");
}

__global__ void __launch_bounds__(NTHREADS, 1)
hs_db_kernel(const float* __restrict__ x,      // (B,T,F,N)
             const float* __restrict__ z0,     // (B,H,N)
             const float* __restrict__ S,      // (B,T,1,N,N)
             const float* __restrict__ aW,     // (H,1,K,F)
             const float* __restrict__ bW,     // (H,1,K,H)
             const float* __restrict__ xBias,  // (H,1)
             const float* __restrict__ zBias,  // (H,1)
             float* __restrict__ out)          // (B,T,H,N)
{
    extern __shared__ float sm[];
    float* sbias = sm + OFF_BIAS;
    uint32_t* sSTw = reinterpret_cast<uint32_t*>(sm + OFF_SST);
    __half*   sSTh = reinterpret_cast<__half*>(sm + OFF_SST);
    uint32_t* sVw  = reinterpret_cast<uint32_t*>(sm + OFF_V);
    __half*   sVh  = reinterpret_cast<__half*>(sm + OFF_V);
    uint32_t* sWw  = reinterpret_cast<uint32_t*>(sm + OFF_W);
    __half*   sWh  = reinterpret_cast<__half*>(sm + OFF_W);

    const int tid  = threadIdx.x;
    const int b    = blockIdx.x / CTAS_PER_B;
    const int col0 = (blockIdx.x % CTAS_PER_B) * COLS_PER_CTA;
    const int kc0  = col0 >> 6;           // this CTA's write chunk (64-wide)
    const int cmb  = col0 & 63;           // 0/16/32/48 within chunk

    // mma mapping (shared by both phases)
    const int wid  = tid >> 5;            // warp 0..7
    const int lane = tid & 31;
    const int gid  = lane >> 2;           // groupID 0..7
    const int tid4 = lane & 3;            // threadID_in_group
    // phase-2 tile: warp -> (m-tile, n-tile)
    const int mt  = wid >> 1;             // 0..3 (h rows 16*mt..)
    const int ntl = wid & 1;              // 0..1 (cols 8*ntl..)

    const uint32_t smem_u32 = (uint32_t)__cvta_generic_to_shared(sm);
    const uint32_t mbar_base = smem_u32 + OFF_MBAR * 4;      // 3 x 8B
    const uint32_t st_base   = smem_u32 + OFF_STATE * 4;

    if (tid == 0) {
#pragma unroll
        for (int s = 0; s < NBUF; ++s) mbar_init(mbar_base + 8 * s, 1);
    }

    // Load fused weights once (fp16): sWh[h][0..127]=aW, [128..383]=bW, pitch PV_H
    for (int i = tid; i < Hn * 128; i += NTHREADS) {
        int h = i >> 7, j = i & 127;
        sWh[h * PV_H + j] = __float2half(aW[i]);
    }
    for (int i = tid; i < Hn * 256; i += NTHREADS) {
        int h = i >> 8, j = i & 255;
        sWh[h * PV_H + 128 + j] = __float2half(bW[i]);
    }
    if (tid < Hn) sbias[tid] = xBias[tid] + zBias[tid];

    // Init: zero this CTA's state columns; sV z-region <- z0 (fp16)
    for (int i = tid; i < SROWS * COLS_PER_CTA; i += NTHREADS) {
        int r = i >> 4, cc = i & 15;
        g_state[0][b][kc0][r][cmb + cc] = __float2half(0.0f);
    }
    for (int i = tid; i < Hn * COLS_PER_CTA; i += NTHREADS) {
        int g = i >> 4, cc = i & 15;
        sVh[cc * PV_H + 128 + g] = __float2half(z0[(b * Hn + g) * Nn + col0 + cc]);
    }

    // TMA ring cursors (continuous across the launch; mbar state is per-launch)
    int psl = 0;                 // producer slot
    int csl = 0; unsigned cph = 0;   // consumer slot/phase

    unsigned lsense = 0;
    grid_barrier(&lsense);   // barrier #1 (orders mbarrier init + state zero)

    for (int t = 0; t < Tn; ++t) {
        const int cur = t & 1;
        const int nxt = cur ^ 1;
        const float* Sbt = S + (size_t)(b * Tn + t) * Nn * Nn;
        const float* xbt = x + (size_t)(b * Tn + t) * Fn * Nn;
        const __half* gst = &g_state[cur][b][0][0][0];

        // prologue: issue chunks 0,1
#pragma unroll
        for (int i = 0; i < 2; ++i) {
            if (tid == 0) {
                mbar_expect_tx(mbar_base + 8 * psl, CHUNK_BYTES);
                bulk_copy(st_base + psl * CHUNK_BYTES,
                          gst + (size_t)i * CHUNK_HALVES, CHUNK_BYTES,
                          mbar_base + 8 * psl);
            }
            psl = (psl + 1 == NBUF) ? 0 : psl + 1;
        }

        // Stage x(t) -> sVh[cc][0..31]
        for (int i = tid; i < Fn * 16; i += NTHREADS) {
            int f = i >> 4, cc = i & 15;
            sVh[cc * PV_H + f] = __float2half(xbt[f * Nn + col0 + cc]);
        }
        // Stage FULL S^T (fp16): sSTh[c][k], k=0..511 (2 k-rows per thread)
#pragma unroll
        for (int r2 = 0; r2 < 2; ++r2) {
            const int k = tid + 256 * r2;
            const float* srow = Sbt + (size_t)k * Nn + col0;
            float4 v0 = *reinterpret_cast<const float4*>(srow);
            float4 v1 = *reinterpret_cast<const float4*>(srow + 4);
            float4 v2 = *reinterpret_cast<const float4*>(srow + 8);
            float4 v3 = *reinterpret_cast<const float4*>(srow + 12);
            float vv[16] = {v0.x, v0.y, v0.z, v0.w, v1.x, v1.y, v1.z, v1.w,
                            v2.x, v2.y, v2.z, v2.w, v3.x, v3.y, v3.z, v3.w};
#pragma unroll
            for (int c = 0; c < 16; ++c)
                sSTh[c * PITCH_SST_H + k] = __float2half(vv[c]);
        }
        __syncthreads();                 // S^T + sV.x ready

        // acc[mgi][nt][4] — full-K fp32 accumulators (phase 1)
        float acc[3][2][4];
#pragma unroll
        for (int i = 0; i < 3; ++i)
#pragma unroll
            for (int n = 0; n < 2; ++n)
#pragma unroll
                for (int q = 0; q < 4; ++q) acc[i][n][q] = 0.0f;

        for (int c = 0; c < NCHUNK; ++c) {
            // keep 3 TMAs in flight: issue chunk c+2 (its slot freed end of c-1)
            if (c < NCHUNK - 2) {
                if (tid == 0) {
                    mbar_expect_tx(mbar_base + 8 * psl, CHUNK_BYTES);
                    bulk_copy(st_base + psl * CHUNK_BYTES,
                              gst + (size_t)(c + 2) * CHUNK_HALVES, CHUNK_BYTES,
                              mbar_base + 8 * psl);
                }
                psl = (psl + 1 == NBUF) ? 0 : psl + 1;
            }
            const int sl = csl;
            mbar_wait(mbar_base + 8 * sl, cph);
            if (++csl == NBUF) { csl = 0; cph ^= 1u; }
            // compute chunk c: 4 k16-steps
            {
                const uint32_t* slotw = reinterpret_cast<const uint32_t*>(sm + OFF_STATE)
                                        + sl * CHUNK_WORDS;
                const int sstkb = 32 * c;             // S^T word base for this chunk
#pragma unroll
                for (int ks = 0; ks < 4; ++ks) {
                    const int aw = 8 * ks + tid4;     // A word offset within 36-word row
                    const int bw = sstkb + 8 * ks + tid4;
                    uint32_t bfr[2][2];
#pragma unroll
                    for (int nt = 0; nt < 2; ++nt) {
                        const uint32_t* bp = sSTw + (8 * nt + gid) * PITCH_SST_W + bw;
                        bfr[nt][0] = bp[0];
                        bfr[nt][1] = bp[4];
                    }
#pragma unroll
                    for (int i = 0; i < 3; ++i) {
                        const int mg = wid + 8 * i;
                        if (mg < 18) {
                            const uint32_t* ap = slotw + (16 * mg + gid) * CPITCH_W + aw;
                            uint32_t a0 = ap[0];
                            uint32_t a1 = ap[8 * CPITCH_W];
                            uint32_t a2 = ap[4];
                            uint32_t a3 = ap[8 * CPITCH_W + 4];
                            mma_f16(acc[i][0][0], acc[i][0][1], acc[i][0][2], acc[i][0][3],
                                    a0, a1, a2, a3, bfr[0][0], bfr[0][1]);
                            mma_f16(acc[i][1][0], acc[i][1][1], acc[i][1][2], acc[i][1][3],
                                    a0, a1, a2, a3, bfr[1][0], bfr[1][1]);
                        }
                    }
                }
            }
            __syncthreads();             // slot-free handoff
        }

        // Write Y (acc, fp16) into col-major sV: row<96 -> j=32+row ; row>=96 -> j=96+row
#pragma unroll
        for (int i = 0; i < 3; ++i) {
            const int mg = wid + 8 * i;
            if (mg < 18) {
                const int r_lo = 16 * mg + gid;
                const int r_hi = r_lo + 8;
                const int j_lo = (r_lo < 96) ? (32 + r_lo) : (96 + r_lo);
                const int j_hi = (r_hi < 96) ? (32 + r_hi) : (96 + r_hi);
#pragma unroll
                for (int nt = 0; nt < 2; ++nt) {
                    const int cl = 8 * nt + 2 * tid4;
                    sVh[cl * PV_H + j_lo]       = __float2half(acc[i][nt][0]);
                    sVh[(cl + 1) * PV_H + j_lo] = __float2half(acc[i][nt][1]);
                    sVh[cl * PV_H + j_hi]       = __float2half(acc[i][nt][2]);
                    sVh[(cl + 1) * PV_H + j_hi] = __float2half(acc[i][nt][3]);
                }
            }
        }
        __syncthreads();

        // ---- Phase 2 via HMMA: pre[64,16] = W[64,384] @ V[384,16] ----
        // warp tile: rows 16*mt..+15, cols 8*ntl..+7; 24 k16-steps
        float pd[4] = {0.0f, 0.0f, 0.0f, 0.0f};
        {
            const uint32_t* apb = sWw + (16 * mt + gid) * PV_W;
            const uint32_t* bpb = sVw + (8 * ntl + gid) * PV_W;
#pragma unroll
            for (int ks = 0; ks < 24; ++ks) {
                const int w0 = 8 * ks + tid4;
                uint32_t a0 = apb[w0];
                uint32_t a1 = apb[8 * PV_W + w0];
                uint32_t a2 = apb[w0 + 4];
                uint32_t a3 = apb[8 * PV_W + w0 + 4];
                mma_f16(pd[0], pd[1], pd[2], pd[3],
                        a0, a1, a2, a3, bpb[w0], bpb[w0 + 4]);
            }
        }
        const int h_lo = 16 * mt + gid;
        const int h_hi = h_lo + 8;
        const int c_0  = 8 * ntl + 2 * tid4;
        float z00 = tanhf(sbias[h_lo] + pd[0]);
        float z01 = tanhf(sbias[h_lo] + pd[1]);
        float z10 = tanhf(sbias[h_hi] + pd[2]);
        float z11 = tanhf(sbias[h_hi] + pd[3]);

        // State shift for t+1 (fp16 copy, column-local)
        {
            __half* gnxt = &g_state[nxt][b][kc0][0][0];
#pragma unroll
            for (int it = 0; it < 18; ++it) {
                int i = tid + it * NTHREADS;
                int r = i >> 4, cc = i & 15;
                int j = (r < 96) ? r : (r + 32);
                gnxt[r * CPITCH_H + cmb + cc] = sVh[cc * PV_H + j];
            }
        }
        __syncthreads();   // all reads of z(t-1) (MMA + shift) done before overwrite

        // write z(t) -> out (fp32) + sV z-region (fp16)
        {
            float* ob = out + ((size_t)(b * Tn + t) * Hn) * Nn + col0;
            ob[(size_t)h_lo * Nn + c_0]     = z00;
            ob[(size_t)h_lo * Nn + c_0 + 1] = z01;
            ob[(size_t)h_hi * Nn + c_0]     = z10;
            ob[(size_t)h_hi * Nn + c_0 + 1] = z11;
            sVh[c_0 * PV_H + 128 + h_lo]       = __float2half(z00);
            sVh[(c_0 + 1) * PV_H + 128 + h_lo] = __float2half(z01);
            sVh[c_0 * PV_H + 128 + h_hi]       = __float2half(z10);
            sVh[(c_0 + 1) * PV_H + 128 + h_hi] = __float2half(z11);
        }

        grid_barrier(&lsense);   // barriers #2..#65
    }

    grid_barrier(&lsense);       // barrier #66 (even parity per launch)
}

extern "C" void kernel_launch(void* const* d_in, const int* in_sizes, int n_in,
                              void* d_out, int out_size) {
    const float* x     = (const float*)d_in[0];
    const float* z0    = (const float*)d_in[1];
    const float* S     = (const float*)d_in[2];
    const float* aW    = (const float*)d_in[3];
    const float* bW    = (const float*)d_in[4];
    const float* xBias = (const float*)d_in[5];
    const float* zBias = (const float*)d_in[6];
    float* out = (float*)d_out;

    cudaFuncSetAttribute(hs_db_kernel,
                         cudaFuncAttributeMaxDynamicSharedMemorySize, SMEM_BYTES);
    hs_db_kernel<<<NCTAS, NTHREADS, SMEM_BYTES>>>(x, z0, S, aW, bW, xBias, zBias, out);
}